// round 5
// baseline (speedup 1.0000x reference)
#include <cuda_runtime.h>
#include <cuda_bf16.h>
#include <math.h>

#define HDIM 256
#define BSEG 4096
#define K1   (3 * HDIM)   // 768

__device__ float g_combined[BSEG * K1];    // [B, 3H] = mean | sum | max
__device__ float g_hidden[BSEG * HDIM];    // [B, H]

__device__ __forceinline__ int lower_bound_i32(const int* __restrict__ a,
                                               int n, int v) {
    int lo = 0, hi = n;
    while (lo < hi) {
        int mid = (lo + hi) >> 1;
        if (a[mid] < v) lo = mid + 1; else hi = mid;
    }
    return lo;
}

// ---------------------------------------------------------------------------
// Stage 1: segment pooling (R3 version — measured 178.5us, 73.6% DRAM).
// 256 threads = 4 row-groups x 64 lanes, float4 per lane, 2 rows in flight.
// ---------------------------------------------------------------------------
__global__ void __launch_bounds__(256)
pool_kernel(const float4* __restrict__ feat4,   // [N, 64] float4
            const int* __restrict__ batch,
            float4* __restrict__ combined4,     // [B, 192] float4 (mean|sum|max)
            int n_rows) {
    const int b = blockIdx.x;
    const int t = threadIdx.x;
    const int g = t >> 6;   // 0..3
    const int c = t & 63;   // 0..63

    __shared__ int s_se[2];
    if (t < 2) s_se[t] = lower_bound_i32(batch, n_rows, b + t);
    __syncthreads();
    const int start = s_se[0];
    const int end   = s_se[1];
    const int cnt   = end - start;

    float4 s0 = make_float4(0.f, 0.f, 0.f, 0.f);
    float4 s1 = make_float4(0.f, 0.f, 0.f, 0.f);
    float4 m0 = make_float4(-INFINITY, -INFINITY, -INFINITY, -INFINITY);
    float4 m1 = m0;

    int i = start + g;
    for (; i + 4 < end; i += 8) {
        float4 v0 = feat4[(size_t)i * 64 + c];
        float4 v1 = feat4[(size_t)(i + 4) * 64 + c];
        s0.x += v0.x; s0.y += v0.y; s0.z += v0.z; s0.w += v0.w;
        s1.x += v1.x; s1.y += v1.y; s1.z += v1.z; s1.w += v1.w;
        m0.x = fmaxf(m0.x, v0.x); m0.y = fmaxf(m0.y, v0.y);
        m0.z = fmaxf(m0.z, v0.z); m0.w = fmaxf(m0.w, v0.w);
        m1.x = fmaxf(m1.x, v1.x); m1.y = fmaxf(m1.y, v1.y);
        m1.z = fmaxf(m1.z, v1.z); m1.w = fmaxf(m1.w, v1.w);
    }
    if (i < end) {
        float4 v0 = feat4[(size_t)i * 64 + c];
        s0.x += v0.x; s0.y += v0.y; s0.z += v0.z; s0.w += v0.w;
        m0.x = fmaxf(m0.x, v0.x); m0.y = fmaxf(m0.y, v0.y);
        m0.z = fmaxf(m0.z, v0.z); m0.w = fmaxf(m0.w, v0.w);
    }
    float4 s = make_float4(s0.x + s1.x, s0.y + s1.y, s0.z + s1.z, s0.w + s1.w);
    float4 m = make_float4(fmaxf(m0.x, m1.x), fmaxf(m0.y, m1.y),
                           fmaxf(m0.z, m1.z), fmaxf(m0.w, m1.w));

    __shared__ float4 red_s[4][64];
    __shared__ float4 red_m[4][64];
    red_s[g][c] = s;
    red_m[g][c] = m;
    __syncthreads();

    if (t < 64) {
        float4 S = red_s[0][t], M = red_m[0][t];
        #pragma unroll
        for (int gg = 1; gg < 4; ++gg) {
            float4 ps = red_s[gg][t], pm = red_m[gg][t];
            S.x += ps.x; S.y += ps.y; S.z += ps.z; S.w += ps.w;
            M.x = fmaxf(M.x, pm.x); M.y = fmaxf(M.y, pm.y);
            M.z = fmaxf(M.z, pm.z); M.w = fmaxf(M.w, pm.w);
        }
        float inv = (cnt > 0) ? (1.0f / (float)cnt) : 0.0f;
        if (cnt == 0) {
            S = make_float4(0.f, 0.f, 0.f, 0.f);
            M = S;
        }
        float4 mean = make_float4(S.x * inv, S.y * inv, S.z * inv, S.w * inv);
        float4* row = combined4 + (size_t)b * 192;
        row[t]       = mean;
        row[64 + t]  = S;
        row[128 + t] = M;
    }
}

// ---------------------------------------------------------------------------
// Stage 2/3: double-buffered SMEM-tiled GEMM with packed fma.rn.f32x2.
// BM=32, BN=64, BK=32, 256 threads, 2x4 microtile -> grid 512 CTAs (3.46/SM).
// ---------------------------------------------------------------------------
__device__ __forceinline__ unsigned long long pack2(float x) {
    unsigned long long r;
    asm("mov.b64 %0, {%1, %1};" : "=l"(r) : "f"(x));
    return r;
}
#define FFMA2(acc, a, b) \
    asm("fma.rn.f32x2 %0, %1, %2, %0;" : "+l"(acc) : "l"(a), "l"(b))

__global__ void __launch_bounds__(256)
gemm_bias_act(const float* __restrict__ A,
              const float* __restrict__ W,
              const float* __restrict__ bias,
              float* __restrict__ C,
              int M, int K, int N, int do_silu) {
    __shared__ float As[2][32][34];  // [buf][k][m], stride 34 (even -> 8B align)
    __shared__ float Bs[2][32][64];  // [buf][k][n]

    const int tid = threadIdx.x;
    const int tx  = tid & 15;       // 0..15 -> 4-col group
    const int ty  = tid >> 4;       // 0..15 -> 2-row group
    const int bm  = blockIdx.y * 32;
    const int bn  = blockIdx.x * 64;

    // A tile: 32(m) x 32(k) floats = 256 float4, 1 per thread
    const int la_r = tid >> 3;            // m 0..31
    const int la_c = (tid & 7) * 4;       // k offset
    // W tile: 32(k) x 64(n) = 512 float4, 2 per thread
    const int lb0_r = tid >> 4,          lb0_n = (tid & 15) * 4;   // k 0..15
    const int lb1_r = 16 + (tid >> 4),   lb1_n = (tid & 15) * 4;   // k 16..31

    const int nk = K >> 5;
    float4 a0, w0, w1;

    a0 = *(const float4*)&A[(size_t)(bm + la_r) * K + la_c];
    w0 = *(const float4*)&W[(size_t)lb0_r * N + bn + lb0_n];
    w1 = *(const float4*)&W[(size_t)lb1_r * N + bn + lb1_n];

    As[0][la_c + 0][la_r] = a0.x; As[0][la_c + 1][la_r] = a0.y;
    As[0][la_c + 2][la_r] = a0.z; As[0][la_c + 3][la_r] = a0.w;
    *(float4*)&Bs[0][lb0_r][lb0_n] = w0;
    *(float4*)&Bs[0][lb1_r][lb1_n] = w1;
    __syncthreads();

    unsigned long long acc2[2][2] = {};   // [row][colpair], packed f32x2

    for (int kk = 0; kk < nk; ++kk) {
        const int buf = kk & 1;
        if (kk + 1 < nk) {
            const int k0 = (kk + 1) << 5;
            a0 = *(const float4*)&A[(size_t)(bm + la_r) * K + k0 + la_c];
            w0 = *(const float4*)&W[(size_t)(k0 + lb0_r) * N + bn + lb0_n];
            w1 = *(const float4*)&W[(size_t)(k0 + lb1_r) * N + bn + lb1_n];
        }

        #pragma unroll
        for (int k = 0; k < 32; ++k) {
            const float2 av = *(const float2*)&As[buf][k][ty * 2];
            const ulonglong2 bp = *(const ulonglong2*)&Bs[buf][k][tx * 4];
            const unsigned long long ap0 = pack2(av.x);
            const unsigned long long ap1 = pack2(av.y);
            FFMA2(acc2[0][0], ap0, bp.x); FFMA2(acc2[0][1], ap0, bp.y);
            FFMA2(acc2[1][0], ap1, bp.x); FFMA2(acc2[1][1], ap1, bp.y);
        }

        if (kk + 1 < nk) {
            const int nb = buf ^ 1;
            As[nb][la_c + 0][la_r] = a0.x; As[nb][la_c + 1][la_r] = a0.y;
            As[nb][la_c + 2][la_r] = a0.z; As[nb][la_c + 3][la_r] = a0.w;
            *(float4*)&Bs[nb][lb0_r][lb0_n] = w0;
            *(float4*)&Bs[nb][lb1_r][lb1_n] = w1;
            __syncthreads();
        }
    }

    const float4 bv4 = *(const float4*)&bias[bn + tx * 4];
    #pragma unroll
    for (int iu = 0; iu < 2; ++iu) {
        const int m = bm + ty * 2 + iu;
        float x0, x1, x2, x3;
        asm("mov.b64 {%0, %1}, %2;" : "=f"(x0), "=f"(x1) : "l"(acc2[iu][0]));
        asm("mov.b64 {%0, %1}, %2;" : "=f"(x2), "=f"(x3) : "l"(acc2[iu][1]));
        x0 += bv4.x; x1 += bv4.y; x2 += bv4.z; x3 += bv4.w;
        if (do_silu) {
            x0 = x0 / (1.0f + __expf(-x0));
            x1 = x1 / (1.0f + __expf(-x1));
            x2 = x2 / (1.0f + __expf(-x2));
            x3 = x3 / (1.0f + __expf(-x3));
        }
        *(float4*)&C[(size_t)m * N + bn + tx * 4] = make_float4(x0, x1, x2, x3);
    }
}

// ---------------------------------------------------------------------------
extern "C" void kernel_launch(void* const* d_in, const int* in_sizes, int n_in,
                              void* d_out, int out_size) {
    const float* feat  = (const float*)d_in[0];
    const int*   batch = (const int*)d_in[1];
    const float* W1    = (const float*)d_in[2];
    const float* b1    = (const float*)d_in[3];
    const float* W2    = (const float*)d_in[4];
    const float* b2    = (const float*)d_in[5];
    float*       out   = (float*)d_out;

    const int n_rows = in_sizes[1];

    float *combined, *hidden;
    cudaGetSymbolAddress((void**)&combined, g_combined);
    cudaGetSymbolAddress((void**)&hidden,   g_hidden);

    pool_kernel<<<BSEG, 256>>>((const float4*)feat, batch,
                               (float4*)combined, n_rows);

    dim3 g1(HDIM / 64, BSEG / 32);   // (4, 128) = 512 CTAs
    gemm_bias_act<<<g1, 256>>>(combined, W1, b1, hidden, BSEG, K1, HDIM, 1);

    dim3 g2(HDIM / 64, BSEG / 32);
    gemm_bias_act<<<g2, 256>>>(hidden, W2, b2, out, BSEG, HDIM, HDIM, 0);
}

// round 6
// speedup vs baseline: 1.1670x; 1.1670x over previous
#include <cuda_runtime.h>
#include <cuda_bf16.h>
#include <math.h>

#define HDIM 256
#define BSEG 4096
#define K1   (3 * HDIM)   // 768

__device__ float g_combined[BSEG * K1];    // [B, 3H] = mean | sum | max
__device__ float g_hidden[BSEG * HDIM];    // [B, H]

__device__ __forceinline__ int lower_bound_i32(const int* __restrict__ a,
                                               int n, int v) {
    int lo = 0, hi = n;
    while (lo < hi) {
        int mid = (lo + hi) >> 1;
        if (a[mid] < v) lo = mid + 1; else hi = mid;
    }
    return lo;
}

__device__ __forceinline__ void acc4(float4& s, float4& m, const float4 v) {
    s.x += v.x; s.y += v.y; s.z += v.z; s.w += v.w;
    m.x = fmaxf(m.x, v.x); m.y = fmaxf(m.y, v.y);
    m.z = fmaxf(m.z, v.z); m.w = fmaxf(m.w, v.w);
}

// ---------------------------------------------------------------------------
// Stage 1: segment pooling. 256 threads = 4 row-groups x 64 lanes, float4 per
// lane, 4 rows in flight (MLP=4) feeding 2 accumulator pairs.
// ---------------------------------------------------------------------------
__global__ void __launch_bounds__(256)
pool_kernel(const float4* __restrict__ feat4,   // [N, 64] float4
            const int* __restrict__ batch,
            float4* __restrict__ combined4,     // [B, 192] float4 (mean|sum|max)
            int n_rows) {
    const int b = blockIdx.x;
    const int t = threadIdx.x;
    const int g = t >> 6;   // 0..3
    const int c = t & 63;   // 0..63

    __shared__ int s_se[2];
    if (t < 2) s_se[t] = lower_bound_i32(batch, n_rows, b + t);
    __syncthreads();
    const int start = s_se[0];
    const int end   = s_se[1];
    const int cnt   = end - start;

    float4 s0 = make_float4(0.f, 0.f, 0.f, 0.f), s1 = s0;
    float4 m0 = make_float4(-INFINITY, -INFINITY, -INFINITY, -INFINITY);
    float4 m1 = m0;

    int i = start + g;
    // 4 independent loads in flight per iteration
    for (; i + 12 < end; i += 16) {
        float4 v0 = feat4[(size_t)(i +  0) * 64 + c];
        float4 v1 = feat4[(size_t)(i +  4) * 64 + c];
        float4 v2 = feat4[(size_t)(i +  8) * 64 + c];
        float4 v3 = feat4[(size_t)(i + 12) * 64 + c];
        acc4(s0, m0, v0); acc4(s1, m1, v1);
        acc4(s0, m0, v2); acc4(s1, m1, v3);
    }
    for (; i < end; i += 4) {
        float4 v = feat4[(size_t)i * 64 + c];
        acc4(s0, m0, v);
    }
    float4 s = make_float4(s0.x + s1.x, s0.y + s1.y, s0.z + s1.z, s0.w + s1.w);
    float4 m = make_float4(fmaxf(m0.x, m1.x), fmaxf(m0.y, m1.y),
                           fmaxf(m0.z, m1.z), fmaxf(m0.w, m1.w));

    __shared__ float4 red_s[4][64];
    __shared__ float4 red_m[4][64];
    red_s[g][c] = s;
    red_m[g][c] = m;
    __syncthreads();

    if (t < 64) {
        float4 S = red_s[0][t], M = red_m[0][t];
        #pragma unroll
        for (int gg = 1; gg < 4; ++gg) {
            float4 ps = red_s[gg][t], pm = red_m[gg][t];
            S.x += ps.x; S.y += ps.y; S.z += ps.z; S.w += ps.w;
            M.x = fmaxf(M.x, pm.x); M.y = fmaxf(M.y, pm.y);
            M.z = fmaxf(M.z, pm.z); M.w = fmaxf(M.w, pm.w);
        }
        float inv = (cnt > 0) ? (1.0f / (float)cnt) : 0.0f;
        if (cnt == 0) {
            S = make_float4(0.f, 0.f, 0.f, 0.f);
            M = S;
        }
        float4 mean = make_float4(S.x * inv, S.y * inv, S.z * inv, S.w * inv);
        float4* row = combined4 + (size_t)b * 192;
        row[t]       = mean;
        row[64 + t]  = S;
        row[128 + t] = M;
    }
}

// ---------------------------------------------------------------------------
// Stage 2/3: double-buffered SMEM-tiled GEMM with packed fma.rn.f32x2.
// BM=32, BN=64, BK=32, 128 threads, 4x4 microtile -> grid 512 (3.46 CTAs/SM).
// Same per-thread inner mix as the R4 BM=64 kernel (16 FFMA2 / 2 LDS / 4 pack)
// but double the CTA count.
// ---------------------------------------------------------------------------
__device__ __forceinline__ unsigned long long pack2(float x) {
    unsigned long long r;
    asm("mov.b64 %0, {%1, %1};" : "=l"(r) : "f"(x));
    return r;
}
#define FFMA2(acc, a, b) \
    asm("fma.rn.f32x2 %0, %1, %2, %0;" : "+l"(acc) : "l"(a), "l"(b))

__global__ void __launch_bounds__(128)
gemm_bias_act(const float* __restrict__ A,
              const float* __restrict__ W,
              const float* __restrict__ bias,
              float* __restrict__ C,
              int M, int K, int N, int do_silu) {
    __shared__ float As[2][32][36];  // [buf][k][m], pad 36 keeps ty*4 16B-aligned
    __shared__ float Bs[2][32][64];  // [buf][k][n]

    const int tid = threadIdx.x;     // 128 threads
    const int tx  = tid & 15;        // 0..15 -> n group (4 cols)
    const int ty  = tid >> 4;        // 0..7  -> m group (4 rows)
    const int bm  = blockIdx.y * 32;
    const int bn  = blockIdx.x * 64;

    // A tile: 32(m) x 32(k) = 256 float4; 2 per thread
    const int la0 = tid,         la0_r = la0 >> 3, la0_c = (la0 & 7) * 4;
    const int la1 = tid + 128,   la1_r = la1 >> 3, la1_c = (la1 & 7) * 4;
    // W tile: 32(k) x 64(n) = 512 float4; 4 per thread
    const int lw_n = (tid & 15) * 4;
    const int lw_r0 = tid >> 4;          // +0,8,16,24

    const int nk = K >> 5;
    float4 a0, a1, w0, w1, w2, w3;

    a0 = *(const float4*)&A[(size_t)(bm + la0_r) * K + la0_c];
    a1 = *(const float4*)&A[(size_t)(bm + la1_r) * K + la1_c];
    w0 = *(const float4*)&W[(size_t)(lw_r0 +  0) * N + bn + lw_n];
    w1 = *(const float4*)&W[(size_t)(lw_r0 +  8) * N + bn + lw_n];
    w2 = *(const float4*)&W[(size_t)(lw_r0 + 16) * N + bn + lw_n];
    w3 = *(const float4*)&W[(size_t)(lw_r0 + 24) * N + bn + lw_n];

    As[0][la0_c + 0][la0_r] = a0.x; As[0][la0_c + 1][la0_r] = a0.y;
    As[0][la0_c + 2][la0_r] = a0.z; As[0][la0_c + 3][la0_r] = a0.w;
    As[0][la1_c + 0][la1_r] = a1.x; As[0][la1_c + 1][la1_r] = a1.y;
    As[0][la1_c + 2][la1_r] = a1.z; As[0][la1_c + 3][la1_r] = a1.w;
    *(float4*)&Bs[0][lw_r0 +  0][lw_n] = w0;
    *(float4*)&Bs[0][lw_r0 +  8][lw_n] = w1;
    *(float4*)&Bs[0][lw_r0 + 16][lw_n] = w2;
    *(float4*)&Bs[0][lw_r0 + 24][lw_n] = w3;
    __syncthreads();

    unsigned long long acc2[4][2] = {};   // [row][colpair] packed f32x2

    for (int kk = 0; kk < nk; ++kk) {
        const int buf = kk & 1;
        if (kk + 1 < nk) {
            const int k0 = (kk + 1) << 5;
            a0 = *(const float4*)&A[(size_t)(bm + la0_r) * K + k0 + la0_c];
            a1 = *(const float4*)&A[(size_t)(bm + la1_r) * K + k0 + la1_c];
            w0 = *(const float4*)&W[(size_t)(k0 + lw_r0 +  0) * N + bn + lw_n];
            w1 = *(const float4*)&W[(size_t)(k0 + lw_r0 +  8) * N + bn + lw_n];
            w2 = *(const float4*)&W[(size_t)(k0 + lw_r0 + 16) * N + bn + lw_n];
            w3 = *(const float4*)&W[(size_t)(k0 + lw_r0 + 24) * N + bn + lw_n];
        }

        #pragma unroll
        for (int k = 0; k < 32; ++k) {
            const float4 av = *(const float4*)&As[buf][k][ty * 4];
            const ulonglong2 bp = *(const ulonglong2*)&Bs[buf][k][tx * 4];
            const unsigned long long ap0 = pack2(av.x);
            const unsigned long long ap1 = pack2(av.y);
            const unsigned long long ap2 = pack2(av.z);
            const unsigned long long ap3 = pack2(av.w);
            FFMA2(acc2[0][0], ap0, bp.x); FFMA2(acc2[0][1], ap0, bp.y);
            FFMA2(acc2[1][0], ap1, bp.x); FFMA2(acc2[1][1], ap1, bp.y);
            FFMA2(acc2[2][0], ap2, bp.x); FFMA2(acc2[2][1], ap2, bp.y);
            FFMA2(acc2[3][0], ap3, bp.x); FFMA2(acc2[3][1], ap3, bp.y);
        }

        if (kk + 1 < nk) {
            const int nb = buf ^ 1;
            As[nb][la0_c + 0][la0_r] = a0.x; As[nb][la0_c + 1][la0_r] = a0.y;
            As[nb][la0_c + 2][la0_r] = a0.z; As[nb][la0_c + 3][la0_r] = a0.w;
            As[nb][la1_c + 0][la1_r] = a1.x; As[nb][la1_c + 1][la1_r] = a1.y;
            As[nb][la1_c + 2][la1_r] = a1.z; As[nb][la1_c + 3][la1_r] = a1.w;
            *(float4*)&Bs[nb][lw_r0 +  0][lw_n] = w0;
            *(float4*)&Bs[nb][lw_r0 +  8][lw_n] = w1;
            *(float4*)&Bs[nb][lw_r0 + 16][lw_n] = w2;
            *(float4*)&Bs[nb][lw_r0 + 24][lw_n] = w3;
            __syncthreads();
        }
    }

    const float4 bv4 = *(const float4*)&bias[bn + tx * 4];
    #pragma unroll
    for (int iu = 0; iu < 4; ++iu) {
        const int m = bm + ty * 4 + iu;
        float x0, x1, x2, x3;
        asm("mov.b64 {%0, %1}, %2;" : "=f"(x0), "=f"(x1) : "l"(acc2[iu][0]));
        asm("mov.b64 {%0, %1}, %2;" : "=f"(x2), "=f"(x3) : "l"(acc2[iu][1]));
        x0 += bv4.x; x1 += bv4.y; x2 += bv4.z; x3 += bv4.w;
        if (do_silu) {
            x0 = x0 / (1.0f + __expf(-x0));
            x1 = x1 / (1.0f + __expf(-x1));
            x2 = x2 / (1.0f + __expf(-x2));
            x3 = x3 / (1.0f + __expf(-x3));
        }
        *(float4*)&C[(size_t)m * N + bn + tx * 4] = make_float4(x0, x1, x2, x3);
    }
}

// ---------------------------------------------------------------------------
extern "C" void kernel_launch(void* const* d_in, const int* in_sizes, int n_in,
                              void* d_out, int out_size) {
    const float* feat  = (const float*)d_in[0];
    const int*   batch = (const int*)d_in[1];
    const float* W1    = (const float*)d_in[2];
    const float* b1    = (const float*)d_in[3];
    const float* W2    = (const float*)d_in[4];
    const float* b2    = (const float*)d_in[5];
    float*       out   = (float*)d_out;

    const int n_rows = in_sizes[1];

    float *combined, *hidden;
    cudaGetSymbolAddress((void**)&combined, g_combined);
    cudaGetSymbolAddress((void**)&hidden,   g_hidden);

    pool_kernel<<<BSEG, 256>>>((const float4*)feat, batch,
                               (float4*)combined, n_rows);

    dim3 g1(HDIM / 64, BSEG / 32);   // (4, 128) = 512 CTAs
    gemm_bias_act<<<g1, 128>>>(combined, W1, b1, hidden, BSEG, K1, HDIM, 1);

    dim3 g2(HDIM / 64, BSEG / 32);
    gemm_bias_act<<<g2, 128>>>(hidden, W2, b2, out, BSEG, HDIM, HDIM, 0);
}

// round 7
// speedup vs baseline: 1.2288x; 1.0529x over previous
#include <cuda_runtime.h>
#include <cuda_bf16.h>
#include <math.h>

#define HDIM 256
#define BSEG 4096
#define K1   (3 * HDIM)   // 768
#define SPLIT1 4          // gemm1 K-split (768 = 4 x 192)
#define SPLIT2 2          // gemm2 K-split (256 = 2 x 128)

__device__ float g_combined[BSEG * K1];          // [B, 3H]
__device__ float g_part[SPLIT1 * BSEG * HDIM];   // split-K partials (max 4)
__device__ float g_hidden[BSEG * HDIM];          // [B, H]

__device__ __forceinline__ int lower_bound_i32(const int* __restrict__ a,
                                               int n, int v) {
    int lo = 0, hi = n;
    while (lo < hi) {
        int mid = (lo + hi) >> 1;
        if (a[mid] < v) lo = mid + 1; else hi = mid;
    }
    return lo;
}

__device__ __forceinline__ void acc4(float4& s, float4& m, const float4 v) {
    s.x += v.x; s.y += v.y; s.z += v.z; s.w += v.w;
    m.x = fmaxf(m.x, v.x); m.y = fmaxf(m.y, v.y);
    m.z = fmaxf(m.z, v.z); m.w = fmaxf(m.w, v.w);
}

// ---------------------------------------------------------------------------
// Stage 1: segment pooling (R6 structure + __ldcs streaming loads).
// ---------------------------------------------------------------------------
__global__ void __launch_bounds__(256)
pool_kernel(const float4* __restrict__ feat4,
            const int* __restrict__ batch,
            float4* __restrict__ combined4,
            int n_rows) {
    const int b = blockIdx.x;
    const int t = threadIdx.x;
    const int g = t >> 6;
    const int c = t & 63;

    __shared__ int s_se[2];
    if (t < 2) s_se[t] = lower_bound_i32(batch, n_rows, b + t);
    __syncthreads();
    const int start = s_se[0];
    const int end   = s_se[1];
    const int cnt   = end - start;

    float4 s0 = make_float4(0.f, 0.f, 0.f, 0.f), s1 = s0;
    float4 m0 = make_float4(-INFINITY, -INFINITY, -INFINITY, -INFINITY);
    float4 m1 = m0;

    int i = start + g;
    for (; i + 12 < end; i += 16) {
        float4 v0 = __ldcs(&feat4[(size_t)(i +  0) * 64 + c]);
        float4 v1 = __ldcs(&feat4[(size_t)(i +  4) * 64 + c]);
        float4 v2 = __ldcs(&feat4[(size_t)(i +  8) * 64 + c]);
        float4 v3 = __ldcs(&feat4[(size_t)(i + 12) * 64 + c]);
        acc4(s0, m0, v0); acc4(s1, m1, v1);
        acc4(s0, m0, v2); acc4(s1, m1, v3);
    }
    for (; i < end; i += 4) {
        float4 v = __ldcs(&feat4[(size_t)i * 64 + c]);
        acc4(s0, m0, v);
    }
    float4 s = make_float4(s0.x + s1.x, s0.y + s1.y, s0.z + s1.z, s0.w + s1.w);
    float4 m = make_float4(fmaxf(m0.x, m1.x), fmaxf(m0.y, m1.y),
                           fmaxf(m0.z, m1.z), fmaxf(m0.w, m1.w));

    __shared__ float4 red_s[4][64];
    __shared__ float4 red_m[4][64];
    red_s[g][c] = s;
    red_m[g][c] = m;
    __syncthreads();

    if (t < 64) {
        float4 S = red_s[0][t], M = red_m[0][t];
        #pragma unroll
        for (int gg = 1; gg < 4; ++gg) {
            float4 ps = red_s[gg][t], pm = red_m[gg][t];
            S.x += ps.x; S.y += ps.y; S.z += ps.z; S.w += ps.w;
            M.x = fmaxf(M.x, pm.x); M.y = fmaxf(M.y, pm.y);
            M.z = fmaxf(M.z, pm.z); M.w = fmaxf(M.w, pm.w);
        }
        float inv = (cnt > 0) ? (1.0f / (float)cnt) : 0.0f;
        if (cnt == 0) { S = make_float4(0.f, 0.f, 0.f, 0.f); M = S; }
        float4 mean = make_float4(S.x * inv, S.y * inv, S.z * inv, S.w * inv);
        float4* row = combined4 + (size_t)b * 192;
        row[t]       = mean;
        row[64 + t]  = S;
        row[128 + t] = M;
    }
}

// ---------------------------------------------------------------------------
// Split-K GEMM: Cpart[z][M,N] = A[M, kb:kb+kc] @ W[kb:kb+kc, N]
// BM=64, BN=64, BK=32, 256 threads, 4x4 f32x2 microtile (proven R4 loop).
// ---------------------------------------------------------------------------
__device__ __forceinline__ unsigned long long pack2(float x) {
    unsigned long long r;
    asm("mov.b64 %0, {%1, %1};" : "=l"(r) : "f"(x));
    return r;
}
#define FFMA2(acc, a, b) \
    asm("fma.rn.f32x2 %0, %1, %2, %0;" : "+l"(acc) : "l"(a), "l"(b))

__global__ void __launch_bounds__(256)
gemm_splitk(const float* __restrict__ A,
            const float* __restrict__ W,
            float* __restrict__ Cpart,
            int M, int K, int N, int k_chunk) {
    __shared__ float As[2][32][68];
    __shared__ float Bs[2][32][64];

    const int tid = threadIdx.x;
    const int tx  = tid & 15;
    const int ty  = tid >> 4;
    const int bm  = blockIdx.y * 64;
    const int bn  = blockIdx.x * 64;
    const int kb  = blockIdx.z * k_chunk;

    const int la0_r = tid >> 3,          la0_c = (tid & 7) * 4;
    const int la1_r = (tid + 256) >> 3,  la1_c = ((tid + 256) & 7) * 4;
    const int lb0_r = tid >> 4,          lb0_n = (tid & 15) * 4;
    const int lb1_r = (tid + 256) >> 4,  lb1_n = ((tid + 256) & 15) * 4;

    const int nk = k_chunk >> 5;
    float4 a0, a1, w0, w1;

    a0 = *(const float4*)&A[(size_t)(bm + la0_r) * K + kb + la0_c];
    a1 = *(const float4*)&A[(size_t)(bm + la1_r) * K + kb + la1_c];
    w0 = *(const float4*)&W[(size_t)(kb + lb0_r) * N + bn + lb0_n];
    w1 = *(const float4*)&W[(size_t)(kb + lb1_r) * N + bn + lb1_n];

    As[0][la0_c + 0][la0_r] = a0.x; As[0][la0_c + 1][la0_r] = a0.y;
    As[0][la0_c + 2][la0_r] = a0.z; As[0][la0_c + 3][la0_r] = a0.w;
    As[0][la1_c + 0][la1_r] = a1.x; As[0][la1_c + 1][la1_r] = a1.y;
    As[0][la1_c + 2][la1_r] = a1.z; As[0][la1_c + 3][la1_r] = a1.w;
    *(float4*)&Bs[0][lb0_r][lb0_n] = w0;
    *(float4*)&Bs[0][lb1_r][lb1_n] = w1;
    __syncthreads();

    unsigned long long acc2[4][2] = {};

    for (int kk = 0; kk < nk; ++kk) {
        const int buf = kk & 1;
        if (kk + 1 < nk) {
            const int k0 = kb + ((kk + 1) << 5);
            a0 = *(const float4*)&A[(size_t)(bm + la0_r) * K + k0 + la0_c];
            a1 = *(const float4*)&A[(size_t)(bm + la1_r) * K + k0 + la1_c];
            w0 = *(const float4*)&W[(size_t)(k0 + lb0_r) * N + bn + lb0_n];
            w1 = *(const float4*)&W[(size_t)(k0 + lb1_r) * N + bn + lb1_n];
        }

        #pragma unroll
        for (int k = 0; k < 32; ++k) {
            const float4 av = *(const float4*)&As[buf][k][ty * 4];
            const ulonglong2 bp = *(const ulonglong2*)&Bs[buf][k][tx * 4];
            const unsigned long long ap0 = pack2(av.x);
            const unsigned long long ap1 = pack2(av.y);
            const unsigned long long ap2 = pack2(av.z);
            const unsigned long long ap3 = pack2(av.w);
            FFMA2(acc2[0][0], ap0, bp.x); FFMA2(acc2[0][1], ap0, bp.y);
            FFMA2(acc2[1][0], ap1, bp.x); FFMA2(acc2[1][1], ap1, bp.y);
            FFMA2(acc2[2][0], ap2, bp.x); FFMA2(acc2[2][1], ap2, bp.y);
            FFMA2(acc2[3][0], ap3, bp.x); FFMA2(acc2[3][1], ap3, bp.y);
        }

        if (kk + 1 < nk) {
            const int nb = buf ^ 1;
            As[nb][la0_c + 0][la0_r] = a0.x; As[nb][la0_c + 1][la0_r] = a0.y;
            As[nb][la0_c + 2][la0_r] = a0.z; As[nb][la0_c + 3][la0_r] = a0.w;
            As[nb][la1_c + 0][la1_r] = a1.x; As[nb][la1_c + 1][la1_r] = a1.y;
            As[nb][la1_c + 2][la1_r] = a1.z; As[nb][la1_c + 3][la1_r] = a1.w;
            *(float4*)&Bs[nb][lb0_r][lb0_n] = w0;
            *(float4*)&Bs[nb][lb1_r][lb1_n] = w1;
            __syncthreads();
        }
    }

    float* Cp = Cpart + (size_t)blockIdx.z * M * N;
    #pragma unroll
    for (int iu = 0; iu < 4; ++iu) {
        const int m = bm + ty * 4 + iu;
        float x0, x1, x2, x3;
        asm("mov.b64 {%0, %1}, %2;" : "=f"(x0), "=f"(x1) : "l"(acc2[iu][0]));
        asm("mov.b64 {%0, %1}, %2;" : "=f"(x2), "=f"(x3) : "l"(acc2[iu][1]));
        *(float4*)&Cp[(size_t)m * N + bn + tx * 4] = make_float4(x0, x1, x2, x3);
    }
}

// ---------------------------------------------------------------------------
// Epilogue: out = (sum over parts) + bias, optional SiLU. One float4/thread.
// ---------------------------------------------------------------------------
__global__ void __launch_bounds__(256)
epilogue(const float4* __restrict__ Cpart,   // [parts][M*N/4]
         const float4* __restrict__ bias4,   // [N/4]
         float4* __restrict__ out4,          // [M*N/4]
         int total4, int parts, int n4, int do_silu) {
    const int idx = blockIdx.x * 256 + threadIdx.x;
    if (idx >= total4) return;
    float4 s = Cpart[idx];
    for (int p = 1; p < parts; ++p) {
        const float4 v = Cpart[(size_t)p * total4 + idx];
        s.x += v.x; s.y += v.y; s.z += v.z; s.w += v.w;
    }
    const float4 bv = bias4[idx & (n4 - 1)];
    s.x += bv.x; s.y += bv.y; s.z += bv.z; s.w += bv.w;
    if (do_silu) {
        s.x = s.x / (1.0f + __expf(-s.x));
        s.y = s.y / (1.0f + __expf(-s.y));
        s.z = s.z / (1.0f + __expf(-s.z));
        s.w = s.w / (1.0f + __expf(-s.w));
    }
    out4[idx] = s;
}

// ---------------------------------------------------------------------------
extern "C" void kernel_launch(void* const* d_in, const int* in_sizes, int n_in,
                              void* d_out, int out_size) {
    const float* feat  = (const float*)d_in[0];
    const int*   batch = (const int*)d_in[1];
    const float* W1    = (const float*)d_in[2];
    const float* b1    = (const float*)d_in[3];
    const float* W2    = (const float*)d_in[4];
    const float* b2    = (const float*)d_in[5];
    float*       out   = (float*)d_out;

    const int n_rows = in_sizes[1];

    float *combined, *part, *hidden;
    cudaGetSymbolAddress((void**)&combined, g_combined);
    cudaGetSymbolAddress((void**)&part,     g_part);
    cudaGetSymbolAddress((void**)&hidden,   g_hidden);

    pool_kernel<<<BSEG, 256>>>((const float4*)feat, batch,
                               (float4*)combined, n_rows);

    const int total4 = BSEG * HDIM / 4;   // 262144
    const int n4 = HDIM / 4;              // 64

    // GEMM1: [4096,768] @ [768,256], split-K 4 (chunks of 192)
    dim3 g1(HDIM / 64, BSEG / 64, SPLIT1);
    gemm_splitk<<<g1, 256>>>(combined, W1, part, BSEG, K1, HDIM, K1 / SPLIT1);
    epilogue<<<(total4 + 255) / 256, 256>>>((const float4*)part,
                                            (const float4*)b1,
                                            (float4*)hidden,
                                            total4, SPLIT1, n4, 1);

    // GEMM2: [4096,256] @ [256,256], split-K 2 (chunks of 128)
    dim3 g2(HDIM / 64, BSEG / 64, SPLIT2);
    gemm_splitk<<<g2, 256>>>(hidden, W2, part, BSEG, HDIM, HDIM, HDIM / SPLIT2);
    epilogue<<<(total4 + 255) / 256, 256>>>((const float4*)part,
                                            (const float4*)b2,
                                            (float4*)out,
                                            total4, SPLIT2, n4, 0);
}